// round 17
// baseline (speedup 1.0000x reference)
#include <cuda_runtime.h>
#include <cuda_bf16.h>
#include <math.h>
#include <stdint.h>

#define NB   1024
#define NN   32
#define HIDD 512
#define DD   400
#define NC   800
#define ADMM_ITERS 40
#define NEWTON_ITERS 8

typedef __nv_bfloat16 bf;

// ---------------- device scratch ----------------
__device__ float g_alpha;
__device__ unsigned g_cnt1, g_gen1, g_cnt2, g_gen2;
__device__ float dKf[DD*DD];
__device__ float dXaf[DD*DD], dXbf[DD*DD];
__device__ float dFKf[NC*DD];
__device__ float dCf_[NB*NC];
__device__ float dbf_[NB*NC];
__device__ float dyf_[NB*NC];
__device__ float dUf_[NB*DD];

__device__ bf X0Th[NB*NN], X0Tl[NB*NN];
__device__ bf W1Th[HIDD*NN], W1Tl[HIDD*NN];
__device__ bf W2Th[HIDD*HIDD], W2Tl[HIDD*HIDD];
__device__ bf W3Th[DD*HIDD], W3Tl[DD*HIDD];
__device__ bf H0h_[NC*NN], H0l_[NC*NN];
__device__ bf Fh_[NC*DD], Fl_[NC*DD];
__device__ bf FTh_[DD*NC], FTl_[DD*NC];
__device__ bf H1h_[NB*HIDD], H1l_[NB*HIDD];
__device__ bf H2h_[NB*HIDD], H2l_[NB*HIDD];
__device__ bf Vh_[NB*DD], Vl_[NB*DD];
__device__ bf Kh_[DD*DD], Kl_[DD*DD];
__device__ bf Xah_[DD*DD], Xal_[DD*DD];
__device__ bf Xbh_[DD*DD], Xbl_[DD*DD];
__device__ bf Yh_[DD*DD], Yl_[DD*DD];
__device__ bf FKh_[NC*DD], FKl_[NC*DD];
__device__ bf FKTh_[DD*NC], FKTl_[DD*NC];
__device__ bf Gh_[NC*NC], Gl_[NC*NC];
__device__ bf Wah_[NB*NC], Wal_[NB*NC];
__device__ bf Wbh_[NB*NC], Wbl_[NB*NC];

// ---------------- PTX helpers ----------------
__device__ __forceinline__ uint32_t smem_u32(const void* p) {
    uint32_t a;
    asm("{ .reg .u64 t; cvta.to.shared.u64 t, %1; cvt.u32.u64 %0, t; }" : "=r"(a) : "l"(p));
    return a;
}
__device__ __forceinline__ void cp16(uint32_t sa, const void* g, int bytes) {
    asm volatile("cp.async.cg.shared.global [%0], [%1], 16, %2;"
                 :: "r"(sa), "l"(g), "r"(bytes) : "memory");
}
#define CP_COMMIT() asm volatile("cp.async.commit_group;" ::: "memory")
#define CP_WAIT1()  asm volatile("cp.async.wait_group 1;" ::: "memory")
#define CP_WAIT0()  asm volatile("cp.async.wait_group 0;" ::: "memory")

__device__ __forceinline__ void ldsm4(uint32_t* r, uint32_t a) {
    asm volatile("ldmatrix.sync.aligned.m8n8.x4.shared.b16 {%0,%1,%2,%3}, [%4];"
                 : "=r"(r[0]), "=r"(r[1]), "=r"(r[2]), "=r"(r[3]) : "r"(a));
}
__device__ __forceinline__ void mma2(float* c, uint32_t a0, uint32_t a1, uint32_t a2,
                                     uint32_t a3, uint32_t b0, uint32_t b1) {
    asm volatile("mma.sync.aligned.m16n8k16.row.col.f32.bf16.bf16.f32 "
                 "{%0,%1,%2,%3},{%4,%5,%6,%7},{%8,%9},{%0,%1,%2,%3};"
                 : "+f"(c[0]), "+f"(c[1]), "+f"(c[2]), "+f"(c[3])
                 : "r"(a0), "r"(a1), "r"(a2), "r"(a3), "r"(b0), "r"(b1));
}
#define SWZ(x) ((x) ^ (((x) >> 3) & 0x70))

__device__ __forceinline__ void gbar(unsigned* cnt, unsigned* gen, unsigned nblk,
                                     unsigned target) {
    __threadfence();
    __syncthreads();
    if (threadIdx.x == 0) {
        unsigned t = atomicAdd(cnt, 1u);
        if (t == nblk - 1u) {
            *cnt = 0u;
            __threadfence();
            atomicAdd(gen, 1u);
        } else {
            while (atomicAdd(gen, 0u) < target) { }
        }
    }
    __syncthreads();
}

// ---------------- generic tensor GEMM (BM=BN=64, 256 thr) ----------------
#define A_HALF (64 * 128)
#define B_HALF (64 * 128)
#define STAGE (2 * A_HALF + 2 * B_HALF)
#define SMEMB (3 * STAGE)

__global__ __launch_bounds__(256, 2) void tgemm(
    const bf* __restrict__ Ah, const bf* __restrict__ Al,
    const bf* __restrict__ Bh, const bf* __restrict__ Bl,
    float* __restrict__ Cf, bf* __restrict__ Ch, bf* __restrict__ Cl,
    long Crs, long Ccs,
    int Md, int Nd, int Kd,
    int epi, const float* __restrict__ e0, const float* __restrict__ e1,
    const float* __restrict__ e2, float* __restrict__ o1)
{
    extern __shared__ char sm[];
    const uint32_t sbase = smem_u32(sm);
    const int tid = threadIdx.x;
    const int wid = tid >> 5, lane = tid & 31;
    const int wm = wid >> 2, wn = wid & 3;
    const int i0 = blockIdx.y * 64, j0 = blockIdx.x * 64;
    const int nch = (Kd + 63) >> 6;

    auto fill = [&](int c) {
        const uint32_t st = sbase + (c % 3) * STAGE;
        const int k0 = c << 6;
#pragma unroll
        for (int t = 0; t < 4; t++) {
            int idx = tid + t * 256;
            int seg = idx & 7, r = (idx >> 3) & 63;
            int mat = idx >> 9;
            int gi = i0 + r, gk = k0 + seg * 8;
            bool ok = (gi < Md) && (gk < Kd);
            const bf* src = (mat ? Al : Ah) + (long)gi * Kd + gk;
            cp16(st + mat * A_HALF + SWZ((uint32_t)(r * 128 + seg * 16)),
                 ok ? (const void*)src : (const void*)Ah, ok ? 16 : 0);
        }
#pragma unroll
        for (int t = 0; t < 4; t++) {
            int idx = tid + t * 256;
            int seg = idx & 7, r = (idx >> 3) & 63;
            int mat = idx >> 9;
            int gj = j0 + r, gk = k0 + seg * 8;
            bool ok = (gj < Nd) && (gk < Kd);
            const bf* src = (mat ? Bl : Bh) + (long)gj * Kd + gk;
            cp16(st + 2 * A_HALF + mat * B_HALF + SWZ((uint32_t)(r * 128 + seg * 16)),
                 ok ? (const void*)src : (const void*)Bh, ok ? 16 : 0);
        }
    };

    float acc[2][2][4];
#pragma unroll
    for (int a = 0; a < 2; a++)
#pragma unroll
        for (int b = 0; b < 2; b++)
#pragma unroll
            for (int r = 0; r < 4; r++) acc[a][b][r] = 0.f;

    const uint32_t arow = (uint32_t)((wm * 32 + (lane & 15)) * 128 + (lane >> 4) * 16);
    const uint32_t brow = (uint32_t)((wn * 16 + (lane & 15)) * 128 + (lane >> 4) * 16);

    fill(0); CP_COMMIT();
    if (nch > 1) fill(1);
    CP_COMMIT();

    for (int c = 0; c < nch; c++) {
        CP_WAIT1();
        __syncthreads();
        if (c + 2 < nch) fill(c + 2);
        CP_COMMIT();

        const uint32_t st = sbase + (c % 3) * STAGE;
#pragma unroll
        for (int ks = 0; ks < 4; ks++) {
            uint32_t bh_[4], bl_[4], ah_[2][4], al_[2][4];
            ldsm4(bh_, st + 2 * A_HALF + SWZ(brow + ks * 32));
            ldsm4(bl_, st + 2 * A_HALF + B_HALF + SWZ(brow + ks * 32));
#pragma unroll
            for (int mt = 0; mt < 2; mt++) {
                ldsm4(ah_[mt], st + SWZ(arow + mt * 2048 + ks * 32));
                ldsm4(al_[mt], st + A_HALF + SWZ(arow + mt * 2048 + ks * 32));
            }
#pragma unroll
            for (int mt = 0; mt < 2; mt++) {
                mma2(acc[mt][0], ah_[mt][0], ah_[mt][1], ah_[mt][2], ah_[mt][3], bh_[0], bh_[2]);
                mma2(acc[mt][1], ah_[mt][0], ah_[mt][1], ah_[mt][2], ah_[mt][3], bh_[1], bh_[3]);
            }
#pragma unroll
            for (int mt = 0; mt < 2; mt++) {
                mma2(acc[mt][0], ah_[mt][0], ah_[mt][1], ah_[mt][2], ah_[mt][3], bl_[0], bl_[2]);
                mma2(acc[mt][1], ah_[mt][0], ah_[mt][1], ah_[mt][2], ah_[mt][3], bl_[1], bl_[3]);
            }
#pragma unroll
            for (int mt = 0; mt < 2; mt++) {
                mma2(acc[mt][0], al_[mt][0], al_[mt][1], al_[mt][2], al_[mt][3], bh_[0], bh_[2]);
                mma2(acc[mt][1], al_[mt][0], al_[mt][1], al_[mt][2], al_[mt][3], bh_[1], bh_[3]);
            }
        }
    }

    const int rbase = i0 + wm * 32 + (lane >> 2);
    const int cb = j0 + wn * 16 + (lane & 3) * 2;
#pragma unroll
    for (int mt = 0; mt < 2; mt++) {
#pragma unroll
        for (int nt = 0; nt < 2; nt++) {
#pragma unroll
            for (int rr = 0; rr < 2; rr++) {
#pragma unroll
                for (int cc = 0; cc < 2; cc++) {
                    int i = rbase + mt * 16 + rr * 8;
                    int j = cb + nt * 8 + cc;
                    if (i >= Md || j >= Nd) continue;
                    float v = acc[mt][nt][rr * 2 + cc];
                    long rm = (long)i * Nd + j;
                    float out;
                    switch (epi) {
                        default:
                        case 0: out = v; break;
                        case 1: out = fmaxf(v + e0[j], 0.f); break;
                        case 2: out = tanhf(v + e0[j]) * e1[j & 7]; break;
                        case 3: out = v + e0[j]; break;
                        case 4: out = fminf(v, e0[rm]); break;
                        case 6: out = 2.f * v; break;
                        case 7: out = (i == j) ? v + 2.f : v; break;
                        case 9: out = v + e0[rm]; break;
                    }
                    if (Cf) Cf[(long)i * Crs + (long)j * Ccs] = out;
                    if (Ch) {
                        bf h16 = __float2bfloat16(out);
                        Ch[rm] = h16;
                        Cl[rm] = __float2bfloat16(out - __bfloat162float(h16));
                    }
                }
            }
        }
    }
    CP_WAIT0();
}

// ---------------- persistent ADMM: BM=128, BN=64, 256 thr, 104 CTAs ----------------
#define AD_TN 13                      // j-tiles: ceil(800/64)
#define AD_BLK 104                    // 8 m-tiles x 13 n-tiles
#define AD_AH (128 * 128)             // one A matrix (hi or lo): 128 rows x 128B
#define AD_BH (64 * 128)
#define AD_STG (2 * AD_AH + 2 * AD_BH)   // 49152
#define AD_SMEM (3 * AD_STG)             // 147456
#define NCH_ADMM 13

__global__ __launch_bounds__(256, 1) void admm_persist(
    const bf* __restrict__ Gh, const bf* __restrict__ Gl,
    const float* __restrict__ Cf, const float* __restrict__ bfv,
    float* __restrict__ yf,
    bf* __restrict__ wah, bf* __restrict__ wal,
    bf* __restrict__ wbh, bf* __restrict__ wbl)
{
    extern __shared__ char sm[];
    const uint32_t sbase = smem_u32(sm);
    const int tid = threadIdx.x;
    const int wid = tid >> 5, lane = tid & 31;
    const int wm = wid >> 1, wn = wid & 1;       // 4 x 2 warp grid, warp tile 32x64? no: 32 rows x 32 cols

    const int i0 = (blockIdx.x / AD_TN) * 128;
    const int j0 = (blockIdx.x % AD_TN) * 64;

    const uint32_t arow = (uint32_t)((wm * 32 + (lane & 15)) * 128 + (lane >> 4) * 16);
    const uint32_t brow = (uint32_t)((wn * 32 + (lane & 15)) * 128 + (lane >> 4) * 16);
    const int rbase = i0 + wm * 32 + (lane >> 2);
    const int cb = j0 + wn * 32 + (lane & 3) * 2;

    for (int t = 0; t < ADMM_ITERS; t++) {
        const bf* Ah = (t & 1) ? wbh : wah;
        const bf* Al = (t & 1) ? wbl : wal;
        bf* Oh = (t & 1) ? wah : wbh;
        bf* Ol = (t & 1) ? wal : wbl;

        auto fill = [&](int c) {
            const uint32_t st = sbase + (c % 3) * AD_STG;
            const int k0 = c << 6;
            // A: 2 mats * 128 rows * 8 segs = 2048 cp (8/thread)
#pragma unroll
            for (int it = 0; it < 8; it++) {
                int idx = tid + it * 256;
                int seg = idx & 7, r = (idx >> 3) & 127;
                int mat = idx >> 10;
                int gi = i0 + r, gk = k0 + seg * 8;
                bool ok = gk < NC;
                const bf* src = (mat ? Al : Ah) + (long)gi * NC + gk;
                cp16(st + mat * AD_AH + SWZ((uint32_t)(r * 128 + seg * 16)),
                     ok ? (const void*)src : (const void*)Ah, ok ? 16 : 0);
            }
            // B: 2 mats * 64 rows * 8 segs = 1024 cp (4/thread)
#pragma unroll
            for (int it = 0; it < 4; it++) {
                int idx = tid + it * 256;
                int seg = idx & 7, r = (idx >> 3) & 63;
                int mat = idx >> 9;
                int gj = j0 + r, gk = k0 + seg * 8;
                bool ok = (gj < NC) && (gk < NC);
                const bf* src = (mat ? Gl : Gh) + (long)gj * NC + gk;
                cp16(st + 2 * AD_AH + mat * AD_BH + SWZ((uint32_t)(r * 128 + seg * 16)),
                     ok ? (const void*)src : (const void*)Gh, ok ? 16 : 0);
            }
        };

        float acc[2][4][4];
#pragma unroll
        for (int a = 0; a < 2; a++)
#pragma unroll
            for (int b = 0; b < 4; b++)
#pragma unroll
                for (int r = 0; r < 4; r++) acc[a][b][r] = 0.f;

        fill(0); CP_COMMIT();
        fill(1); CP_COMMIT();

        uint32_t ah_[2][2][4], al_[2][2][4], bh_[2][2][4], bl_[2][2][4];

        for (int c = 0; c < NCH_ADMM; c++) {
            CP_WAIT1();
            __syncthreads();
            if (c + 2 < NCH_ADMM) fill(c + 2);
            CP_COMMIT();

            const uint32_t st = sbase + (c % 3) * AD_STG;
            // preload ks=0 into buffer 0
#pragma unroll
            for (int g = 0; g < 2; g++) {
                ldsm4(bh_[0][g], st + 2 * AD_AH + SWZ(brow + g * 2048));
                ldsm4(bl_[0][g], st + 2 * AD_AH + AD_BH + SWZ(brow + g * 2048));
            }
#pragma unroll
            for (int mt = 0; mt < 2; mt++) {
                ldsm4(ah_[0][mt], st + SWZ(arow + mt * 2048));
                ldsm4(al_[0][mt], st + AD_AH + SWZ(arow + mt * 2048));
            }
#pragma unroll
            for (int ks = 0; ks < 4; ks++) {
                const int cur = ks & 1, nxt = cur ^ 1;
                if (ks < 3) {
#pragma unroll
                    for (int g = 0; g < 2; g++) {
                        ldsm4(bh_[nxt][g], st + 2 * AD_AH + SWZ(brow + g * 2048 + (ks + 1) * 32));
                        ldsm4(bl_[nxt][g], st + 2 * AD_AH + AD_BH + SWZ(brow + g * 2048 + (ks + 1) * 32));
                    }
#pragma unroll
                    for (int mt = 0; mt < 2; mt++) {
                        ldsm4(ah_[nxt][mt], st + SWZ(arow + mt * 2048 + (ks + 1) * 32));
                        ldsm4(al_[nxt][mt], st + AD_AH + SWZ(arow + mt * 2048 + (ks + 1) * 32));
                    }
                }
                // product-major: hh, hl, lh — 24 MMAs, acc reuse distance 8
#pragma unroll
                for (int mt = 0; mt < 2; mt++)
#pragma unroll
                    for (int g = 0; g < 2; g++) {
                        mma2(acc[mt][g * 2 + 0], ah_[cur][mt][0], ah_[cur][mt][1],
                             ah_[cur][mt][2], ah_[cur][mt][3], bh_[cur][g][0], bh_[cur][g][2]);
                        mma2(acc[mt][g * 2 + 1], ah_[cur][mt][0], ah_[cur][mt][1],
                             ah_[cur][mt][2], ah_[cur][mt][3], bh_[cur][g][1], bh_[cur][g][3]);
                    }
#pragma unroll
                for (int mt = 0; mt < 2; mt++)
#pragma unroll
                    for (int g = 0; g < 2; g++) {
                        mma2(acc[mt][g * 2 + 0], ah_[cur][mt][0], ah_[cur][mt][1],
                             ah_[cur][mt][2], ah_[cur][mt][3], bl_[cur][g][0], bl_[cur][g][2]);
                        mma2(acc[mt][g * 2 + 1], ah_[cur][mt][0], ah_[cur][mt][1],
                             ah_[cur][mt][2], ah_[cur][mt][3], bl_[cur][g][1], bl_[cur][g][3]);
                    }
#pragma unroll
                for (int mt = 0; mt < 2; mt++)
#pragma unroll
                    for (int g = 0; g < 2; g++) {
                        mma2(acc[mt][g * 2 + 0], al_[cur][mt][0], al_[cur][mt][1],
                             al_[cur][mt][2], al_[cur][mt][3], bh_[cur][g][0], bh_[cur][g][2]);
                        mma2(acc[mt][g * 2 + 1], al_[cur][mt][0], al_[cur][mt][1],
                             al_[cur][mt][2], al_[cur][mt][3], bh_[cur][g][1], bh_[cur][g][3]);
                    }
            }
        }
        CP_WAIT0();

        // epilogue: s = acc + C + y ; y = max(s-b, 0) ; w = s - 2y (hi/lo split)
#pragma unroll
        for (int mt = 0; mt < 2; mt++) {
#pragma unroll
            for (int g = 0; g < 2; g++) {
#pragma unroll
                for (int h = 0; h < 2; h++) {
#pragma unroll
                    for (int rr = 0; rr < 2; rr++) {
                        int i = rbase + mt * 16 + rr * 8;
                        int j = cb + g * 16 + h * 8;
                        if (j >= NC) continue;
                        long rm = (long)i * NC + j;
                        float2 cf = *(const float2*)&Cf[rm];
                        float2 yv = *(const float2*)&yf[rm];
                        float2 bv = *(const float2*)&bfv[rm];
                        float s0 = acc[mt][g * 2 + h][rr * 2 + 0] + cf.x + yv.x;
                        float s1 = acc[mt][g * 2 + h][rr * 2 + 1] + cf.y + yv.y;
                        float yn0 = fmaxf(s0 - bv.x, 0.f);
                        float yn1 = fmaxf(s1 - bv.y, 0.f);
                        float o0 = s0 - 2.f * yn0;
                        float o1v = s1 - 2.f * yn1;
                        *(float2*)&yf[rm] = make_float2(yn0, yn1);
                        bf h0 = __float2bfloat16(o0);
                        bf h1 = __float2bfloat16(o1v);
                        bf l0 = __float2bfloat16(o0 - __bfloat162float(h0));
                        bf l1 = __float2bfloat16(o1v - __bfloat162float(h1));
                        uint32_t ph = ((uint32_t)*(uint16_t*)&h1 << 16) | *(uint16_t*)&h0;
                        uint32_t pl = ((uint32_t)*(uint16_t*)&l1 << 16) | *(uint16_t*)&l0;
                        *(uint32_t*)&Oh[rm] = ph;
                        *(uint32_t*)&Ol[rm] = pl;
                    }
                }
            }
        }
        if (t + 1 < ADMM_ITERS) gbar(&g_cnt1, &g_gen1, AD_BLK, (unsigned)(t + 1));
    }
}

// ---------------- persistent Newton-Schulz: 32x32 tiles, 169 CTAs ----------------
#define NW_BLK 169
#define NW_AH (32 * 128)
#define NW_STG (4 * NW_AH)
#define NW_SMEM (3 * NW_STG)

__global__ __launch_bounds__(128, 4) void newton_persist(
    const bf* __restrict__ Kh, const bf* __restrict__ Kl,
    float* __restrict__ Xaf, float* __restrict__ Xbf,
    bf* __restrict__ Xah, bf* __restrict__ Xal,
    bf* __restrict__ Xbh, bf* __restrict__ Xbl,
    bf* __restrict__ Yh, bf* __restrict__ Yl)
{
    extern __shared__ char sm[];
    const uint32_t sbase = smem_u32(sm);
    const int tid = threadIdx.x;
    const int wid = tid >> 5, lane = tid & 31;
    const int wm = wid >> 1, wn = wid & 1;
    const int i0 = (blockIdx.x / 13) * 32;
    const int j0 = (blockIdx.x % 13) * 32;

    const uint32_t arow = (uint32_t)((wm * 16 + (lane & 15)) * 128 + (lane >> 4) * 16);
    const uint32_t brow = (uint32_t)((wn * 16 + (lane & 15)) * 128 + (lane >> 4) * 16);
    const int rb0 = i0 + wm * 16 + (lane >> 2);
    const int cb0 = j0 + wn * 16 + (lane & 3) * 2;

    unsigned bt = 0;

    auto run_gemm = [&](const bf* Ah, const bf* Al, const bf* Bh, const bf* Bl,
                        int mode, const float* Xcf, float* Xnf, bf* Oh, bf* Ol) {
        auto fill = [&](int c) {
            const uint32_t st = sbase + (c % 3) * NW_STG;
            const int k0 = c << 6;
#pragma unroll
            for (int it = 0; it < 4; it++) {
                int idx = tid + it * 128;
                int seg = idx & 7, r = (idx >> 3) & 31;
                int mat = idx >> 8;
                int gi = i0 + r, gk = k0 + seg * 8;
                bool ok = (gi < DD) && (gk < DD);
                const bf* src = (mat ? Al : Ah) + (long)gi * DD + gk;
                cp16(st + mat * NW_AH + SWZ((uint32_t)(r * 128 + seg * 16)),
                     ok ? (const void*)src : (const void*)Ah, ok ? 16 : 0);
            }
#pragma unroll
            for (int it = 0; it < 4; it++) {
                int idx = tid + it * 128;
                int seg = idx & 7, r = (idx >> 3) & 31;
                int mat = idx >> 8;
                int gj = j0 + r, gk = k0 + seg * 8;
                bool ok = (gj < DD) && (gk < DD);
                const bf* src = (mat ? Bl : Bh) + (long)gj * DD + gk;
                cp16(st + 2 * NW_AH + mat * NW_AH + SWZ((uint32_t)(r * 128 + seg * 16)),
                     ok ? (const void*)src : (const void*)Bh, ok ? 16 : 0);
            }
        };

        float acc[2][4];
#pragma unroll
        for (int b = 0; b < 2; b++)
#pragma unroll
            for (int r = 0; r < 4; r++) acc[b][r] = 0.f;

        const int nch = 7;
        fill(0); CP_COMMIT();
        fill(1); CP_COMMIT();

        for (int c = 0; c < nch; c++) {
            CP_WAIT1();
            __syncthreads();
            if (c + 2 < nch) fill(c + 2);
            CP_COMMIT();

            const uint32_t st = sbase + (c % 3) * NW_STG;
#pragma unroll
            for (int ks = 0; ks < 4; ks++) {
                uint32_t ah_[4], al_[4], bh_[4], bl_[4];
                ldsm4(bh_, st + 2 * NW_AH + SWZ(brow + ks * 32));
                ldsm4(bl_, st + 3 * NW_AH + SWZ(brow + ks * 32));
                ldsm4(ah_, st + SWZ(arow + ks * 32));
                ldsm4(al_, st + NW_AH + SWZ(arow + ks * 32));
                mma2(acc[0], ah_[0], ah_[1], ah_[2], ah_[3], bh_[0], bh_[2]);
                mma2(acc[1], ah_[0], ah_[1], ah_[2], ah_[3], bh_[1], bh_[3]);
                mma2(acc[0], ah_[0], ah_[1], ah_[2], ah_[3], bl_[0], bl_[2]);
                mma2(acc[1], ah_[0], ah_[1], ah_[2], ah_[3], bl_[1], bl_[3]);
                mma2(acc[0], al_[0], al_[1], al_[2], al_[3], bh_[0], bh_[2]);
                mma2(acc[1], al_[0], al_[1], al_[2], al_[3], bh_[1], bh_[3]);
            }
        }
        CP_WAIT0();

#pragma unroll
        for (int nt = 0; nt < 2; nt++) {
#pragma unroll
            for (int rr = 0; rr < 2; rr++) {
                int i = rb0 + rr * 8;
                int j = cb0 + nt * 8;
                if (i >= DD || j >= DD) continue;
                long rm = (long)i * DD + j;
                float v0 = acc[nt][rr * 2 + 0];
                float v1 = acc[nt][rr * 2 + 1];
                float o0, o1v;
                if (mode == 0) { o0 = v0; o1v = v1; }
                else {
                    float2 xc = *(const float2*)&Xcf[rm];
                    o0 = 2.f * xc.x - v0;
                    o1v = 2.f * xc.y - v1;
                    *(float2*)&Xnf[rm] = make_float2(o0, o1v);
                }
                bf h0 = __float2bfloat16(o0);
                bf h1 = __float2bfloat16(o1v);
                bf l0 = __float2bfloat16(o0 - __bfloat162float(h0));
                bf l1 = __float2bfloat16(o1v - __bfloat162float(h1));
                uint32_t ph = ((uint32_t)*(uint16_t*)&h1 << 16) | *(uint16_t*)&h0;
                uint32_t pl = ((uint32_t)*(uint16_t*)&l1 << 16) | *(uint16_t*)&l0;
                *(uint32_t*)&Oh[rm] = ph;
                *(uint32_t*)&Ol[rm] = pl;
            }
        }
    };

    for (int it = 0; it < NEWTON_ITERS; it++) {
        const bf* Ach = (it & 1) ? Xbh : Xah;
        const bf* Acl = (it & 1) ? Xbl : Xal;
        const float* Xcf = (it & 1) ? Xbf : Xaf;
        float* Xnf = (it & 1) ? Xaf : Xbf;
        bf* Xnh = (it & 1) ? Xah : Xbh;
        bf* Xnl = (it & 1) ? Xal : Xbl;

        run_gemm(Ach, Acl, Kh, Kl, 0, nullptr, nullptr, Yh, Yl);
        gbar(&g_cnt2, &g_gen2, NW_BLK, ++bt);
        run_gemm(Yh, Yl, Ach, Acl, 1, Xcf, Xnf, Xnh, Xnl);
        if (it + 1 < NEWTON_ITERS) gbar(&g_cnt2, &g_gen2, NW_BLK, ++bt);
    }
}

// ---------------- prep / small kernels ----------------
__device__ __forceinline__ void split_one(float x, bf* h, bf* l, long o) {
    bf b = __float2bfloat16(x);
    h[o] = b;
    l[o] = __float2bfloat16(x - __bfloat162float(b));
}
__global__ void prep_all(const float* __restrict__ X0, const float* __restrict__ W1,
                         const float* __restrict__ W2, const float* __restrict__ W3,
                         const float* __restrict__ H0, const float* __restrict__ F,
                         bf* x0th, bf* x0tl, bf* w1th, bf* w1tl, bf* w2th, bf* w2tl,
                         bf* w3th, bf* w3tl, bf* h0h, bf* h0l, bf* fh, bf* fl,
                         bf* fth, bf* ftl, float* yzero)
{
    long idx = (long)blockIdx.x * blockDim.x + threadIdx.x;
    const long n0 = NN * NB, n1 = NN * HIDD, n2 = HIDD * HIDD, n3 = HIDD * DD;
    const long n4 = NC * NN, n5 = (long)NC * DD, n6 = (long)NC * DD;
    const long n7 = (long)NB * NC;
    if (idx < n0) {
        int r = idx / NB, c = idx - (long)r * NB;
        split_one(X0[idx], x0th, x0tl, (long)c * NN + r);
        return;
    }
    idx -= n0;
    if (idx < n1) {
        int r = idx / HIDD, c = idx - (long)r * HIDD;
        split_one(W1[idx], w1th, w1tl, (long)c * NN + r);
        return;
    }
    idx -= n1;
    if (idx < n2) {
        int r = idx / HIDD, c = idx - (long)r * HIDD;
        split_one(W2[idx], w2th, w2tl, (long)c * HIDD + r);
        return;
    }
    idx -= n2;
    if (idx < n3) {
        int r = idx / DD, c = idx - (long)r * DD;
        split_one(W3[idx], w3th, w3tl, (long)c * HIDD + r);
        return;
    }
    idx -= n3;
    if (idx < n4) { split_one(H0[idx], h0h, h0l, idx); return; }
    idx -= n4;
    if (idx < n5) { split_one(F[idx], fh, fl, idx); return; }
    idx -= n5;
    if (idx < n6) {
        int r = idx / DD, c = idx - (long)r * DD;
        split_one(F[idx], fth, ftl, (long)c * NC + r);
        return;
    }
    idx -= n6;
    if (idx < n7) { yzero[idx] = 0.f; return; }
}
__global__ void init_sync() { g_cnt1 = 0u; g_gen1 = 0u; g_cnt2 = 0u; g_gen2 = 0u; }
__global__ void transpose_split(const float* __restrict__ s, bf* __restrict__ h,
                                bf* __restrict__ l, int R, int C) {
    long i = (long)blockIdx.x * blockDim.x + threadIdx.x;
    if (i < (long)R * C) {
        int r = i / C, c = i - (long)r * C;
        split_one(s[i], h, l, (long)c * R + r);
    }
}
__global__ void gershgorin_kernel(const float* __restrict__ K, int n) {
    __shared__ float red[512];
    float mx = 0.f;
    for (int i = threadIdx.x; i < n; i += blockDim.x) {
        float sum = 0.f;
        for (int j = 0; j < n; j++) sum += fabsf(K[i * n + j]);
        mx = fmaxf(mx, sum);
    }
    red[threadIdx.x] = mx;
    __syncthreads();
    for (int s = 256; s > 0; s >>= 1) {
        if (threadIdx.x < s) red[threadIdx.x] = fmaxf(red[threadIdx.x], red[threadIdx.x + s]);
        __syncthreads();
    }
    if (threadIdx.x == 0) g_alpha = 2.f / (2.f + red[0]);
}
__global__ void init_diag_split(float* __restrict__ Xf, bf* __restrict__ Xh,
                                bf* __restrict__ Xl, int n) {
    int idx = blockIdx.x * blockDim.x + threadIdx.x;
    if (idx < n * n) {
        int i = idx / n, j = idx - i * n;
        float v = (i == j) ? g_alpha : 0.f;
        Xf[idx] = v;
        bf b = __float2bfloat16(v);
        Xh[idx] = b;
        Xl[idx] = __float2bfloat16(v - __bfloat162float(b));
    }
}

// ---------------- host ----------------
static inline void tg(const bf* Ah, const bf* Al, const bf* Bh, const bf* Bl,
                      float* Cf, bf* Ch, bf* Cl, long Crs, long Ccs,
                      int M, int N, int K, int epi,
                      const float* e0 = nullptr, const float* e1 = nullptr,
                      const float* e2 = nullptr, float* o1 = nullptr)
{
    dim3 grid((N + 63) / 64, (M + 63) / 64);
    tgemm<<<grid, 256, SMEMB>>>(Ah, Al, Bh, Bl, Cf, Ch, Cl, Crs, Ccs,
                                M, N, K, epi, e0, e1, e2, o1);
}

template <typename T> static inline T* sym(const void* s) {
    void* p = nullptr;
    cudaGetSymbolAddress(&p, s);
    return (T*)p;
}

extern "C" void kernel_launch(void* const* d_in, const int* in_sizes, int n_in,
                              void* d_out, int out_size)
{
    const float* X0   = (const float*)d_in[0];
    const float* W1   = (const float*)d_in[1];
    const float* b1   = (const float*)d_in[2];
    const float* W2   = (const float*)d_in[3];
    const float* b2   = (const float*)d_in[4];
    const float* W3   = (const float*)d_in[5];
    const float* b3   = (const float*)d_in[6];
    const float* ubar = (const float*)d_in[7];
    const float* F    = (const float*)d_in[8];
    const float* gg   = (const float*)d_in[9];
    const float* H0   = (const float*)d_in[10];
    float* out = (float*)d_out;

    cudaFuncSetAttribute(tgemm, cudaFuncAttributeMaxDynamicSharedMemorySize, SMEMB);
    cudaFuncSetAttribute(admm_persist, cudaFuncAttributeMaxDynamicSharedMemorySize, AD_SMEM);
    cudaFuncSetAttribute(newton_persist, cudaFuncAttributeMaxDynamicSharedMemorySize, NW_SMEM);

    float *pKf = sym<float>(dKf), *pXaf = sym<float>(dXaf), *pXbf = sym<float>(dXbf);
    float *pFKf = sym<float>(dFKf), *pCf = sym<float>(dCf_), *pbf = sym<float>(dbf_);
    float *pyf = sym<float>(dyf_), *pUf = sym<float>(dUf_);

    bf *x0th = sym<bf>(X0Th), *x0tl = sym<bf>(X0Tl);
    bf *w1th = sym<bf>(W1Th), *w1tl = sym<bf>(W1Tl);
    bf *w2th = sym<bf>(W2Th), *w2tl = sym<bf>(W2Tl);
    bf *w3th = sym<bf>(W3Th), *w3tl = sym<bf>(W3Tl);
    bf *h0h = sym<bf>(H0h_), *h0l = sym<bf>(H0l_);
    bf *fh = sym<bf>(Fh_), *fl = sym<bf>(Fl_);
    bf *fth = sym<bf>(FTh_), *ftl = sym<bf>(FTl_);
    bf *h1h = sym<bf>(H1h_), *h1l = sym<bf>(H1l_);
    bf *h2h = sym<bf>(H2h_), *h2l = sym<bf>(H2l_);
    bf *vh = sym<bf>(Vh_), *vl = sym<bf>(Vl_);
    bf *kh = sym<bf>(Kh_), *kl = sym<bf>(Kl_);
    bf *xah = sym<bf>(Xah_), *xal = sym<bf>(Xal_);
    bf *xbh = sym<bf>(Xbh_), *xbl = sym<bf>(Xbl_);
    bf *yh = sym<bf>(Yh_), *yl = sym<bf>(Yl_);
    bf *fkh = sym<bf>(FKh_), *fkl = sym<bf>(FKl_);
    bf *fkth = sym<bf>(FKTh_), *fktl = sym<bf>(FKTl_);
    bf *ghh = sym<bf>(Gh_), *gll = sym<bf>(Gl_);
    bf *wah = sym<bf>(Wah_), *wal = sym<bf>(Wal_);
    bf *wbh = sym<bf>(Wbh_), *wbl = sym<bf>(Wbl_);

    // fused prep (+ y zero) + sync counters
    {
        long total = (long)NN*NB + (long)NN*HIDD + (long)HIDD*HIDD + (long)HIDD*DD
                   + (long)NC*NN + (long)NC*DD + (long)NC*DD + (long)NB*NC;
        prep_all<<<(int)((total + 255) / 256), 256>>>(
            X0, W1, W2, W3, H0, F,
            x0th, x0tl, w1th, w1tl, w2th, w2tl, w3th, w3tl,
            h0h, h0l, fh, fl, fth, ftl, pyf);
    }
    init_sync<<<1, 1>>>();

    // MLP head
    tg(x0th, x0tl, w1th, w1tl, nullptr, h1h, h1l, HIDD, 1, NB, HIDD, NN, 1, b1);
    tg(h1h, h1l, w2th, w2tl, nullptr, h2h, h2l, HIDD, 1, NB, HIDD, HIDD, 1, b2);
    tg(h2h, h2l, w3th, w3tl, nullptr, vh, vl, DD, 1, NB, DD, HIDD, 2, b3, ubar);

    // b = g + X0^T H0^T
    tg(x0th, x0tl, h0h, h0l, pbf, nullptr, nullptr, NC, 1, NB, NC, NN, 3, gg);

    // K = 2I + F^T F
    tg(fth, ftl, fth, ftl, pKf, kh, kl, DD, 1, DD, DD, NC, 7);

    // Kinv: persistent Newton-Schulz (8 iters -> result in xa)
    gershgorin_kernel<<<1, 512>>>(pKf, DD);
    init_diag_split<<<(DD*DD + 255)/256, 256>>>(pXaf, xah, xal, DD);
    newton_persist<<<NW_BLK, 128, NW_SMEM>>>(kh, kl, pXaf, pXbf,
                                             xah, xal, xbh, xbl, yh, yl);

    // precompute: FK, FKT, G, C
    tg(fh, fl, xah, xal, pFKf, fkh, fkl, DD, 1, NC, DD, DD, 0);
    transpose_split<<<(NC*DD + 255)/256, 256>>>(pFKf, fkth, fktl, NC, DD);
    tg(fkh, fkl, fh, fl, nullptr, ghh, gll, NC, 1, NC, NC, DD, 0);
    tg(vh, vl, fkh, fkl, pCf, nullptr, nullptr, NC, 1, NB, NC, DD, 6);

    // init: w0 = min(V F^T, b)
    tg(vh, vl, fh, fl, nullptr, wah, wal, NC, 1, NB, NC, DD, 4, pbf);

    // ADMM: persistent, 40 iters, one 128x64 tile per CTA (104 CTAs, all resident)
    admm_persist<<<AD_BLK, 256, AD_SMEM>>>(ghh, gll, pCf, pbf, pyf,
                                           wah, wal, wbh, wbl);
    // even iters -> final w in wah/wal

    // u = 2 V Kinv + w FK ; out = u^T
    tg(vh, vl, xah, xal, pUf, nullptr, nullptr, DD, 1, NB, DD, DD, 6);
    tg(wah, wal, fkth, fktl, out, nullptr, nullptr, 1, NB, NB, DD, NC, 9, pUf);
}